// round 7
// baseline (speedup 1.0000x reference)
#include <cuda_runtime.h>

#define DIM 4096
#define NQ 12
#define DEPTH 4

// CNOT-ring permutation, gather form (verified rounds 1-4):
// bit_i = x_i ^ x_{i+1} (i<=9), bit10 = x10^x11^x0, bit11 = x11^x0. GF(2)-linear.
__host__ __device__ __forceinline__ constexpr int sig(int x) {
    int r = (x ^ (x >> 1)) & 0x3FF;
    r |= (((x >> 10) ^ (x >> 11) ^ x) & 1) << 10;
    r |= (((x >> 11) ^ x) & 1) << 11;
    return r;
}
// S0 placement: linear XOR fold, reads ONLY bits 5-7, writes bits 0-2.
// Conflict-free for: B-store/init (lanes vary bits 3-7), A-load w/ sigma
// (lane image spans bits 3-8 injectively), readout w/ sigma (bits 0-4).
// Linear => composes/distributes over XOR; k<<8 offsets fold to '+'.
__host__ __device__ __forceinline__ constexpr int PP2(int y) {
    return y ^ ((y >> 5) & 1) ^ (((y >> 6) & 1) << 1) ^ (((y >> 7) & 1) << 2);
}

__global__ __launch_bounds__(256, 1)
void qsim_kernel(const float* __restrict__ x, const float* __restrict__ theta,
                 const float* __restrict__ w, const float* __restrict__ b,
                 float* __restrict__ out) {
    __shared__ float S0[DIM];          // inter-layer buffer (PP2 placement)
    __shared__ float S1[DIM + 132];    // intra-layer buffer (skew i + (i>>5))
    __shared__ float CS[DEPTH * NQ];
    __shared__ float SN[DEPTH * NQ];
    __shared__ float red[16];

    const int tid = threadIdx.x;
    const int lane = tid & 31;
    const int wid = tid >> 5;          // 0..7

    // half-angle cos/sin: angle[d][q] = theta[d][q] + 0.1*x[q]
    if (tid < DEPTH * NQ) {
        const int q = tid % NQ;
        float s, c;
        __sincosf(0.5f * (theta[tid] + 0.1f * x[q]), &s, &c);
        CS[tid] = c;
        SN[tid] = s;
    }
    __syncthreads();

    // Layout A: i = wid<<9 | lane<<4 | k   (k bits 0-3, lane bits 4-8, wid 9-11)
    // Layout B: i = k<<8 | lane<<3 | wid   (wid bits 0-2, lane bits 3-7, k bits 8-11)
    const int baseA = (wid << 9) | (lane << 4);
    const int baseB = (lane << 3) | wid;
    const int sA = baseA + (baseA >> 5);        // S1 A-store base: [sA + k]
    const int sB = baseB + (baseB >> 5);        // S1 B-load  base: [sB + 264k]
    const int pB = PP2(baseB);                  // S0 B-store base: [pB + 256k]
    const int aLb = PP2(sig(baseA));            // S0 A-load base (sigma fused)

    // d-invariant A-load addresses (sig(k) only touches bits {0-3,10,11})
    int aL[16];
#pragma unroll
    for (int k = 0; k < 16; ++k) aL[k] = aLb ^ sig(k);

    float v[16];

    // ============ Layer 0: product state (all 12 RYs applied to e0) ============
    // state bit bp -> qubit 11-bp
    {
        float P = 1.f;
#pragma unroll
        for (int bp = 0; bp < 8; ++bp)
            P *= ((baseB >> bp) & 1) ? SN[11 - bp] : CS[11 - bp];
        float t01[4], t23[4];
#pragma unroll
        for (int t = 0; t < 4; ++t) {
            t01[t] = ((t & 1) ? SN[3] : CS[3]) * ((t & 2) ? SN[2] : CS[2]);
            t23[t] = ((t & 1) ? SN[1] : CS[1]) * ((t & 2) ? SN[0] : CS[0]);
        }
#pragma unroll
        for (int k = 0; k < 16; ++k)
            S0[pB + (k << 8)] = P * t01[k & 3] * t23[k >> 2];
    }
    __syncthreads();

    // ============ Layers 1..3 ============
#pragma unroll
    for (int d = 1; d < DEPTH; ++d) {
        const float* C = CS + d * NQ;
        const float* Sn = SN + d * NQ;

        // ---- Pass A: gather from S0 (prev ring fused), rotate state bits 0-3
        //      (qubits 11,10,9,8; in-reg) + bits 4,5 (qubits 7,6; shfl), store S1
#pragma unroll
        for (int k = 0; k < 16; ++k) v[k] = S0[aL[k]];

#pragma unroll
        for (int rb = 0; rb < 4; ++rb) {       // k bit rb -> qubit 11-rb
            const int m = 1 << rb;
            const float c = C[11 - rb], s = Sn[11 - rb];
#pragma unroll
            for (int k = 0; k < 16; ++k)
                if (!(k & m)) {
                    const float lo = v[k], hi = v[k | m];
                    v[k]     = c * lo - s * hi;
                    v[k | m] = s * lo + c * hi;
                }
        }
#pragma unroll
        for (int bs = 0; bs < 2; ++bs) {       // lane bit bs -> qubit 7-bs
            const int m = 1 << bs;
            const float c = C[7 - bs], s = Sn[7 - bs];
            const float se = (lane & m) ? s : -s;
#pragma unroll
            for (int k = 0; k < 16; ++k) {
                const float o = __shfl_xor_sync(0xffffffffu, v[k], m);
                v[k] = c * v[k] + se * o;
            }
        }
#pragma unroll
        for (int k = 0; k < 16; ++k) S1[sA + k] = v[k];
        __syncthreads();

        // ---- Pass B: load S1, rotate state bits 6,7 (qubits 5,4; shfl on lane
        //      bits 3,4) + bits 8-11 (qubits 3,2,1,0; in-reg), store S0
#pragma unroll
        for (int k = 0; k < 16; ++k) v[k] = S1[sB + 264 * k];

#pragma unroll
        for (int bs = 3; bs < 5; ++bs) {       // lane bit bs -> state bit 3+bs -> qubit 8-bs
            const int m = 1 << bs;
            const float c = C[8 - bs], s = Sn[8 - bs];
            const float se = (lane & m) ? s : -s;
#pragma unroll
            for (int k = 0; k < 16; ++k) {
                const float o = __shfl_xor_sync(0xffffffffu, v[k], m);
                v[k] = c * v[k] + se * o;
            }
        }
#pragma unroll
        for (int rb = 0; rb < 4; ++rb) {       // k bit rb -> state bit 8+rb -> qubit 3-rb
            const int m = 1 << rb;
            const float c = C[3 - rb], s = Sn[3 - rb];
#pragma unroll
            for (int k = 0; k < 16; ++k)
                if (!(k & m)) {
                    const float lo = v[k], hi = v[k | m];
                    v[k]     = c * lo - s * hi;
                    v[k | m] = s * lo + c * hi;
                }
        }
#pragma unroll
        for (int k = 0; k < 16; ++k) S0[pB + (k << 8)] = v[k];
        __syncthreads();
    }

    // ============ Readout (final CNOT ring fused into gather) ============
    // r = wid<<9 | k<<5 | lane  (coalesced global access)
    const int baseR = (wid << 9) | lane;
    const int rb0 = PP2(sig(baseR));
    float a0 = 0.f, a1 = 0.f;
#pragma unroll
    for (int k = 0; k < 16; ++k) {
        const int r = baseR | (k << 5);
        const float vv = S0[rb0 ^ PP2(sig(k << 5))];
        out[2 + r] = vv;
        const float p = vv * vv;
        a0 += p * w[r];
        a1 += p * w[DIM + r];
    }
#pragma unroll
    for (int o = 16; o > 0; o >>= 1) {
        a0 += __shfl_down_sync(0xffffffffu, a0, o);
        a1 += __shfl_down_sync(0xffffffffu, a1, o);
    }
    if (lane == 0) { red[wid] = a0; red[8 + wid] = a1; }
    __syncthreads();
    if (wid == 0 && lane < 16) {
        float r0 = red[lane & 7];
        float r1 = red[8 + (lane & 7)];
        // lanes 0-7 reduce a0, lanes 8-15 reduce a1 — do scalar tree on lane 0/8
        float rr = (lane < 8) ? r0 : r1;
#pragma unroll
        for (int o = 4; o > 0; o >>= 1)
            rr += __shfl_down_sync(0x0000ffffu, rr, o);
        if (lane == 0) out[0] = rr + b[0];
        if (lane == 8) out[1] = rr + b[1];
    }
}

extern "C" void kernel_launch(void* const* d_in, const int* in_sizes, int n_in,
                              void* d_out, int out_size) {
    const float* x = nullptr;
    const float* th = nullptr;
    const float* w = nullptr;
    const float* b = nullptr;
    for (int i = 0; i < n_in; ++i) {
        const int s = in_sizes[i];
        if (s == NQ) x = (const float*)d_in[i];
        else if (s == DEPTH * NQ) th = (const float*)d_in[i];
        else if (s == 2 * DIM) w = (const float*)d_in[i];
        else if (s == 2) b = (const float*)d_in[i];
    }
    qsim_kernel<<<1, 256>>>(x, th, w, b, (float*)d_out);
}